// round 13
// baseline (speedup 1.0000x reference)
#include <cuda_runtime.h>
#include <cuda_fp16.h>
#include <cstdint>

#define HDIM  2048
#define MROWS 16384
#define BM    128
#define BN    128
#define BK    64
#define KSPLIT 2          // split-K for symmetric X^T X
#define NTILE (HDIM / BM) // 16
#define NTRI  (NTILE * (NTILE + 1) / 2)   // 136
#define NRED  (NTILE * NTILE)             // 256 (gemm3 grid)

#define TILE_BYTES  (128 * 128)          // 16KB: 128 rows x 128B (64 fp16)
#define STAGE       (2 * TILE_BYTES)     // stage: A B (32KB)
#define SMEM_DYN    (3 * STAGE + 1024)   // 3-stage pipeline (~97KB); occ=2 fits

// ---------------- device scratch (no allocs allowed) ----------------
__device__ __half g_xhi [(size_t)MROWS * HDIM];
__device__ __half g_xthi[(size_t)MROWS * HDIM];   // x^T [H, M] fp16
__device__ __half g_whi [(size_t)HDIM * HDIM];    // fp16(fw+pw)
__device__ __half g_ghi [(size_t)HDIM * HDIM];    // fp16(G = X^T X)
__device__ float  g_part[(size_t)KSPLIT * HDIM * HDIM];  // G split-K partials
__device__ float  g_colsum[HDIM];                 // colsum(X)
__device__ double g_partials[NRED];
__device__ float  g_scale;

// ---------------- PTX helpers (baseline sm_80+ features only) ----------------
__device__ __forceinline__ uint32_t smem_u32(const void* p) {
    uint32_t a;
    asm("{ .reg .u64 t; cvta.to.shared.u64 t, %1; cvt.u32.u64 %0, t; }" : "=r"(a) : "l"(p));
    return a;
}
__device__ __forceinline__ uint32_t sw128(uint32_t o) { return o ^ ((o >> 3) & 0x70); }

__device__ __forceinline__ void cpasync16(uint32_t d, const void* s) {
    asm volatile("cp.async.cg.shared.global [%0], [%1], 16;" :: "r"(d), "l"(s));
}
#define CP_COMMIT() asm volatile("cp.async.commit_group;" ::: "memory")
#define CP_WAIT1()  asm volatile("cp.async.wait_group 1;" ::: "memory")
#define CP_WAIT0()  asm volatile("cp.async.wait_group 0;" ::: "memory")

__device__ __forceinline__ void ldsm4(uint32_t* r, uint32_t addr) {
    asm volatile("ldmatrix.sync.aligned.m8n8.x4.shared.b16 {%0,%1,%2,%3}, [%4];"
                 : "=r"(r[0]), "=r"(r[1]), "=r"(r[2]), "=r"(r[3]) : "r"(addr));
}
__device__ __forceinline__ void mma16816(float* c, const uint32_t* a, const uint32_t* b) {
    asm volatile(
        "mma.sync.aligned.m16n8k16.row.col.f32.f16.f16.f32 "
        "{%0,%1,%2,%3}, {%4,%5,%6,%7}, {%8,%9}, {%0,%1,%2,%3};"
        : "+f"(c[0]), "+f"(c[1]), "+f"(c[2]), "+f"(c[3])
        : "r"(a[0]), "r"(a[1]), "r"(a[2]), "r"(a[3]), "r"(b[0]), "r"(b[1]));
}

// ---------------- prep kernels ----------------
__global__ void xprep_kernel(const float* __restrict__ in,
                             __half* __restrict__ rh, __half* __restrict__ th,
                             int R, int C) {
    __shared__ float t[32][33];
    int tid = threadIdx.x;                 // 256
    int r0 = blockIdx.y * 32, c0 = blockIdx.x * 32;
    int row = tid >> 3, seg = tid & 7;
    float4 v = *(const float4*)(in + (size_t)(r0 + row) * C + c0 + seg * 4);
    {
        size_t ob = ((size_t)(r0 + row) * C + c0 + seg * 4) >> 1;
        __half2* ph = (__half2*)rh + ob;
        ph[0] = __halves2half2(__float2half(v.x), __float2half(v.y));
        ph[1] = __halves2half2(__float2half(v.z), __float2half(v.w));
    }
    t[row][seg * 4 + 0] = v.x; t[row][seg * 4 + 1] = v.y;
    t[row][seg * 4 + 2] = v.z; t[row][seg * 4 + 3] = v.w;
    __syncthreads();
    int oc = row;
    int rs = seg * 4;
    __half h0 = __float2half(t[rs + 0][oc]);
    __half h1 = __float2half(t[rs + 1][oc]);
    __half h2 = __float2half(t[rs + 2][oc]);
    __half h3 = __float2half(t[rs + 3][oc]);
    size_t ob = ((size_t)(c0 + oc) * R + r0 + rs) >> 1;
    __half2* ph = (__half2*)th + ob;
    ph[0] = __halves2half2(h0, h1); ph[1] = __halves2half2(h2, h3);
}

__global__ void wsum_hi_kernel(const float* __restrict__ fw, const float* __restrict__ pw,
                               __half* __restrict__ oh) {
    size_t i = (size_t)blockIdx.x * blockDim.x + threadIdx.x;
    float4 a = ((const float4*)fw)[i];
    float4 b = ((const float4*)pw)[i];
    __half2* ph = (__half2*)oh + i * 2;
    ph[0] = __halves2half2(__float2half(a.x + b.x), __float2half(a.y + b.y));
    ph[1] = __halves2half2(__float2half(a.z + b.z), __float2half(a.w + b.w));
}

// colsum over x^T rows: s[h] = sum_m xthi[h][m]  (one block per h)
__global__ void colsum_kernel(const __half* __restrict__ xt, float* __restrict__ s, int M) {
    __shared__ float sh[256];
    const int h = blockIdx.x, tid = threadIdx.x;
    const __half2* row = (const __half2*)(xt + (size_t)h * M);
    float acc = 0.f;
    for (int i = tid; i < M / 2; i += 256) {
        float2 v = __half22float2(row[i]);
        acc += v.x + v.y;
    }
    sh[tid] = acc;
    __syncthreads();
    for (int off = 128; off > 0; off >>= 1) {
        if (tid < off) sh[tid] += sh[tid + off];
        __syncthreads();
    }
    if (tid == 0) s[h] = sh[0];
}

// G = P0 + P1 -> fp16
__global__ void gsum_hi_kernel(__half* __restrict__ gh) {
    size_t i = (size_t)blockIdx.x * blockDim.x + threadIdx.x;   // float4 index
    const size_t stride4 = (size_t)HDIM * HDIM / 4;
    float4 a = ((const float4*)g_part)[i];
    float4 b = ((const float4*)g_part)[i + stride4];
    __half2* ph = (__half2*)gh + i * 2;
    ph[0] = __halves2half2(__float2half(a.x + b.x), __float2half(a.y + b.y));
    ph[1] = __halves2half2(__float2half(a.z + b.z), __float2half(a.w + b.w));
}

// ---------------- HMMA mainloop: single-product fp16, 3-stage pipeline ------
// ONE __syncthreads per chunk: CP_WAIT(c) -> sync -> issue(c+2) -> compute(c).
// The sync proves all warps finished compute(c-1) on stage (c-1)%3, which is
// exactly the stage issue(c+2) overwrites ((c+2)%3 == (c-1)%3).
__device__ __forceinline__ void mm_loop(float acc[4][4][4],
    const __half* __restrict__ A, const __half* __restrict__ B,
    int lda, int ldb, int m0, int n0, int kbeg, int NC)
{
    constexpr uint32_t A_OFF = 0;
    constexpr uint32_t B_OFF = TILE_BYTES;

    extern __shared__ char dsm[];
    uint32_t raw = smem_u32(dsm);
    uint32_t sbase = (raw + 1023) & ~1023u;

    const int tid  = threadIdx.x;
    const int lane = tid & 31;
    const int wid  = tid >> 5;
    const int wm = (wid >> 2) * 64;
    const int wn = (wid & 3) * 32;

    const int arow  = wm + (lane & 15);
    const int akadd = (lane >> 4) << 3;
    const int nrow  = wn + (lane & 7) + ((lane >> 4) << 3);
    const int bkadd = ((lane >> 3) & 1) << 3;

    auto issue = [&](int c) {
        uint32_t sb = sbase + (uint32_t)(c % 3) * STAGE;
        const int k0 = kbeg + c * BK;
        #pragma unroll
        for (int t = 0; t < 4; t++) {
            int seg = tid + t * 256;
            int r = seg >> 3, sc = seg & 7;
            uint32_t so = sw128((uint32_t)(r * 128 + sc * 16));
            size_t ga = (size_t)(m0 + r) * lda + k0 + sc * 8;
            size_t gb = (size_t)(n0 + r) * ldb + k0 + sc * 8;
            cpasync16(sb + A_OFF + so, A + ga);
            cpasync16(sb + B_OFF + so, B + gb);
        }
    };

    issue(0); CP_COMMIT();
    if (NC > 1) { issue(1); CP_COMMIT(); }

    #pragma unroll 1
    for (int c = 0; c < NC; c++) {
        if (c + 1 < NC) { CP_WAIT1(); }
        else            { CP_WAIT0(); }
        __syncthreads();
        if (c + 2 < NC) { issue(c + 2); CP_COMMIT(); }

        uint32_t st = sbase + (uint32_t)(c % 3) * STAGE;
        #pragma unroll
        for (int ks = 0; ks < 4; ks++) {
            uint32_t ah[4][4], bh[4][2];
            #pragma unroll
            for (int mi = 0; mi < 4; mi++) {
                uint32_t off = sw128((uint32_t)((arow + mi * 16) * 128 + (ks * 16 + akadd) * 2));
                ldsm4(ah[mi], st + A_OFF + off);
            }
            #pragma unroll
            for (int ng = 0; ng < 2; ng++) {
                uint32_t off = sw128((uint32_t)((nrow + ng * 16) * 128 + (ks * 16 + bkadd) * 2));
                uint32_t q[4];
                ldsm4(q, st + B_OFF + off);
                bh[2*ng][0] = q[0]; bh[2*ng][1] = q[1];
                bh[2*ng+1][0] = q[2]; bh[2*ng+1][1] = q[3];
            }
            #pragma unroll
            for (int mi = 0; mi < 4; mi++)
                #pragma unroll
                for (int ni = 0; ni < 4; ni++)
                    mma16816(acc[mi][ni], ah[mi], bh[ni]);
        }
    }
}

#define ACC_INIT(acc) \
    _Pragma("unroll") for (int i = 0; i < 4; i++) \
    _Pragma("unroll") for (int j = 0; j < 4; j++) \
    _Pragma("unroll") for (int q = 0; q < 4; q++) acc[i][j][q] = 0.f;

// ---------------- GEMM1: combined = xhi @ whi^T + bias ----------------
__global__ __launch_bounds__(256, 2)
void gemm1_mma(const float* __restrict__ bias, float* __restrict__ Cout) {
    float acc[4][4][4];
    ACC_INIT(acc)
    const int m0 = blockIdx.y * BM, n0 = blockIdx.x * BN;
    mm_loop(acc, g_xhi, g_whi, HDIM, HDIM, m0, n0, 0, HDIM / BK);

    const int lane = threadIdx.x & 31, wid = threadIdx.x >> 5;
    const int wm = (wid >> 2) * 64, wn = (wid & 3) * 32;
    const int rbase = m0 + wm + (lane >> 2);
    const int cbase = n0 + wn + (lane & 3) * 2;
    #pragma unroll
    for (int mi = 0; mi < 4; mi++)
        #pragma unroll
        for (int ni = 0; ni < 4; ni++) {
            int r = rbase + mi * 16, cc = cbase + ni * 8;
            float2 bv = *(const float2*)(bias + cc);
            *(float2*)(Cout + (size_t)r * HDIM + cc) =
                make_float2(acc[mi][ni][0] + bv.x, acc[mi][ni][1] + bv.y);
            *(float2*)(Cout + (size_t)(r + 8) * HDIM + cc) =
                make_float2(acc[mi][ni][2] + bv.x, acc[mi][ni][3] + bv.y);
        }
}

// ---------------- GEMM2sym: P[s] += Xt[bi] @ Xt[bj]^T (lower triangle) ------
__global__ __launch_bounds__(256, 2)
void gemm2s_mma(int M) {
    float acc[4][4][4];
    ACC_INIT(acc)

    // triangular decode: blockIdx.x -> (bi, bj), bi >= bj
    int t = blockIdx.x;
    int bi = 0;
    while ((bi + 1) * (bi + 2) / 2 <= t) bi++;
    int bj = t - bi * (bi + 1) / 2;

    const int s = blockIdx.z;
    const int kper = M / KSPLIT;
    const int h0 = bi * BM, n0 = bj * BN;
    mm_loop(acc, g_xthi, g_xthi, M, M, h0, n0, s * kper, kper / BK);

    float* P = g_part + (size_t)s * HDIM * HDIM;
    const int lane = threadIdx.x & 31, wid = threadIdx.x >> 5;
    const int wm = (wid >> 2) * 64, wn = (wid & 3) * 32;
    const int rl = lane >> 2;
    const int cl = (lane & 3) * 2;

    #pragma unroll
    for (int mi = 0; mi < 4; mi++)
        #pragma unroll
        for (int ni = 0; ni < 4; ni++) {
            int r = h0 + wm + rl + mi * 16, cc = n0 + wn + cl + ni * 8;
            *(float2*)(P + (size_t)r * HDIM + cc) =
                make_float2(acc[mi][ni][0], acc[mi][ni][1]);
            *(float2*)(P + (size_t)(r + 8) * HDIM + cc) =
                make_float2(acc[mi][ni][2], acc[mi][ni][3]);
        }

    if (bi != bj) {
        extern __shared__ char dsm[];
        uint32_t raw = smem_u32(dsm);
        char* smp = dsm + (((raw + 1023) & ~1023u) - raw);
        float* tb = (float*)smp + (size_t)wid * (32 * 66);
        __syncthreads();   // mainloop smem fully consumed
        #pragma unroll
        for (int mi = 0; mi < 4; mi++)
            #pragma unroll
            for (int ni = 0; ni < 4; ni++) {
                int lr = rl + mi * 16;
                int lc = cl + ni * 8;
                tb[(lc + 0) * 66 + lr]     = acc[mi][ni][0];
                tb[(lc + 1) * 66 + lr]     = acc[mi][ni][1];
                tb[(lc + 0) * 66 + lr + 8] = acc[mi][ni][2];
                tb[(lc + 1) * 66 + lr + 8] = acc[mi][ni][3];
            }
        __syncwarp();
        const float* src = tb + lane * 66;
        float* dst = P + (size_t)(n0 + wn + lane) * HDIM + h0 + wm;
        #pragma unroll
        for (int j = 0; j < 16; j++) {
            float4 v;
            v.x = src[j * 4 + 0]; v.y = src[j * 4 + 1];
            v.z = src[j * 4 + 2]; v.w = src[j * 4 + 3];
            *(float4*)(dst + j * 4) = v;
        }
    }
}

// ---------------- GEMM3: neww = plastic + factor*(G@Wsum^T + s b^T);
// epilogue also emits sum-of-squares partials ----------------
__global__ __launch_bounds__(256, 2)
void gemm3_mma(const float* __restrict__ plastic,
               const float* __restrict__ rate, const float* __restrict__ hs,
               const float* __restrict__ bias,
               float* __restrict__ Wout, float invM) {
    __shared__ double shred[256];
    float acc[4][4][4];
    ACC_INIT(acc)
    const int m0 = blockIdx.y * BM, n0 = blockIdx.x * BN;
    mm_loop(acc, g_ghi, g_whi, HDIM, HDIM, m0, n0, 0, HDIM / BK);

    const float factor = rate[0] * hs[0] * invM;
    const int lane = threadIdx.x & 31, wid = threadIdx.x >> 5;
    const int wm = (wid >> 2) * 64, wn = (wid & 3) * 32;
    const int rbase = m0 + wm + (lane >> 2);
    const int cbase = n0 + wn + (lane & 3) * 2;
    double ss = 0.0;
    #pragma unroll
    for (int mi = 0; mi < 4; mi++)
        #pragma unroll
        for (int ni = 0; ni < 4; ni++) {
            int r = rbase + mi * 16, cc = cbase + ni * 8;
            float2 bv = *(const float2*)(bias + cc);
            float s0 = g_colsum[r], s1 = g_colsum[r + 8];
            float2 p0 = *(const float2*)(plastic + (size_t)r * HDIM + cc);
            float2 p1 = *(const float2*)(plastic + (size_t)(r + 8) * HDIM + cc);
            float v0 = p0.x + factor * (acc[mi][ni][0] + s0 * bv.x);
            float v1 = p0.y + factor * (acc[mi][ni][1] + s0 * bv.y);
            float v2 = p1.x + factor * (acc[mi][ni][2] + s1 * bv.x);
            float v3 = p1.y + factor * (acc[mi][ni][3] + s1 * bv.y);
            *(float2*)(Wout + (size_t)r * HDIM + cc)       = make_float2(v0, v1);
            *(float2*)(Wout + (size_t)(r + 8) * HDIM + cc) = make_float2(v2, v3);
            ss += (double)v0 * v0 + (double)v1 * v1
                + (double)v2 * v2 + (double)v3 * v3;
        }
    shred[threadIdx.x] = ss;
    __syncthreads();
    for (int off = 128; off > 0; off >>= 1) {
        if (threadIdx.x < off) shred[threadIdx.x] += shred[threadIdx.x + off];
        __syncthreads();
    }
    if (threadIdx.x == 0)
        g_partials[blockIdx.y * NTILE + blockIdx.x] = shred[0];
}

// ---------------- norm finalize + scale ----------------
__global__ void finalize_kernel() {
    __shared__ double sh[256];
    const int tid = threadIdx.x;
    double s = (tid < NRED) ? g_partials[tid] : 0.0;
    sh[tid] = s;
    __syncthreads();
    for (int off = 128; off > 0; off >>= 1) {
        if (tid < off) sh[tid] += sh[tid + off];
        __syncthreads();
    }
    if (tid == 0) {
        double norm = sqrt(sh[0]);
        g_scale = (norm > 1.0) ? (float)(1.0 / norm) : 1.0f;
    }
}

__global__ void scale_kernel(float* __restrict__ W) {
    size_t i = (size_t)blockIdx.x * blockDim.x + threadIdx.x;
    const float s = g_scale;
    float4 v = ((float4*)W)[i];
    v.x *= s; v.y *= s; v.z *= s; v.w *= s;
    ((float4*)W)[i] = v;
}

// ---------------- launch (two-stream fork/join, graph-capturable) -----------
extern "C" void kernel_launch(void* const* d_in, const int* in_sizes, int n_in,
                              void* d_out, int out_size) {
    const float* x    = (const float*)d_in[0];  // [M, H]
    const float* pw   = (const float*)d_in[1];  // [H, H]
    const float* rate = (const float*)d_in[2];  // [1]
    const float* fw   = (const float*)d_in[3];  // [H, H]
    const float* fb   = (const float*)d_in[4];  // [H]
    const float* hs   = (const float*)d_in[5];  // scalar

    const int M = in_sizes[0] / HDIM;           // 16384
    float* combined = (float*)d_out;
    float* neww     = (float*)d_out + (size_t)M * HDIM;

    static bool init_done = false;
    static cudaStream_t s2;
    static cudaEvent_t evFork, evJoin;
    if (!init_done) {
        cudaFuncSetAttribute(gemm1_mma,  cudaFuncAttributeMaxDynamicSharedMemorySize, SMEM_DYN);
        cudaFuncSetAttribute(gemm2s_mma, cudaFuncAttributeMaxDynamicSharedMemorySize, SMEM_DYN);
        cudaFuncSetAttribute(gemm3_mma,  cudaFuncAttributeMaxDynamicSharedMemorySize, SMEM_DYN);
        cudaStreamCreateWithFlags(&s2, cudaStreamNonBlocking);
        cudaEventCreateWithFlags(&evFork, cudaEventDisableTiming);
        cudaEventCreateWithFlags(&evJoin, cudaEventDisableTiming);
        init_done = true;
    }

    __half *xhi, *xthi, *whi, *ghi;
    float* cs;
    cudaGetSymbolAddress((void**)&xhi,  g_xhi);
    cudaGetSymbolAddress((void**)&xthi, g_xthi);
    cudaGetSymbolAddress((void**)&whi,  g_whi);
    cudaGetSymbolAddress((void**)&ghi,  g_ghi);
    cudaGetSymbolAddress((void**)&cs,   g_colsum);

    // prep on the captured (default) stream
    wsum_hi_kernel<<<HDIM * HDIM / 4 / 256, 256>>>(fw, pw, whi);
    {
        dim3 g(HDIM / 32, M / 32);
        xprep_kernel<<<g, 256>>>(x, xhi, xthi, M, HDIM);
    }

    // fork: side stream computes the whole new_w chain
    cudaEventRecord(evFork, 0);
    cudaStreamWaitEvent(s2, evFork, 0);

    colsum_kernel<<<HDIM, 256, 0, s2>>>(xthi, cs, M);
    {
        dim3 g(NTRI, 1, KSPLIT);
        gemm2s_mma<<<g, 256, SMEM_DYN, s2>>>(M);
    }
    gsum_hi_kernel<<<HDIM * HDIM / 4 / 256, 256, 0, s2>>>(ghi);
    {
        dim3 g(NTILE, NTILE);
        gemm3_mma<<<g, 256, SMEM_DYN, s2>>>(pw, rate, hs, fb, neww, 1.0f / (float)M);
    }
    finalize_kernel<<<1, 256, 0, s2>>>();
    scale_kernel<<<HDIM * HDIM / 4 / 256, 256, 0, s2>>>(neww);

    // main stream: GEMM1 (combined) runs concurrently with the s2 chain
    {
        dim3 g(HDIM / BN, M / BM);
        gemm1_mma<<<g, 256, SMEM_DYN>>>(fb, combined);
    }

    // join
    cudaEventRecord(evJoin, s2);
    cudaStreamWaitEvent(0, evJoin, 0);
}